// round 6
// baseline (speedup 1.0000x reference)
#include <cuda_runtime.h>
#include <cuda_bf16.h>
#include <cstdint>
#include <cstddef>

// ---------------------------------------------------------------------------
// TreeRNNCell: out = tanh( mask*(x@W_in + b_in) + segsum(h[src]->dst)@W_aggr + b_aggr )
// N = 500000, E = 500000, X = H = 128.
//
// R5 (re-run; R5 bench was an infra failure): warp-MMA GEMM rebalanced:
//     warp tile 32x64 (was 16x128) -> 12 LDSM.x4 per 48 MMAs per k-step;
//     LDSM batched ahead of MMAs for ILP.
// ---------------------------------------------------------------------------

#define MAXN 500000
__device__ float g_agg[(size_t)MAXN * 128];
// 4 images: [WinT_hi, WinT_lo, WaggrT_hi, WaggrT_lo], each [128n][128k] bf16
__device__ __align__(16) unsigned int g_wimg[4 * 8192];

__device__ __forceinline__ float tanh_fast(float x) {
    float r; asm("tanh.approx.f32 %0, %1;" : "=f"(r) : "f"(x)); return r;
}
__device__ __forceinline__ uint32_t smem_u32(const void* p) {
    uint32_t a;
    asm("{ .reg .u64 t; cvta.to.shared.u64 t, %1; cvt.u32.u64 %0, t; }" : "=r"(a) : "l"(p));
    return a;
}
__device__ __forceinline__ uint32_t pack_split(float a, float b, uint32_t& lo) {
    __nv_bfloat16 ha = __float2bfloat16(a), hb = __float2bfloat16(b);
    __nv_bfloat16 la = __float2bfloat16(a - __bfloat162float(ha));
    __nv_bfloat16 lb = __float2bfloat16(b - __bfloat162float(hb));
    lo = ((uint32_t)__bfloat16_as_ushort(lb) << 16) | __bfloat16_as_ushort(la);
    return ((uint32_t)__bfloat16_as_ushort(hb) << 16) | __bfloat16_as_ushort(ha);
}

#define LDSM_X4(r0, r1, r2, r3, addr) \
    asm volatile("ldmatrix.sync.aligned.m8n8.x4.shared.b16 {%0,%1,%2,%3}, [%4];" \
                 : "=r"(r0), "=r"(r1), "=r"(r2), "=r"(r3) : "r"(addr))

#define MMA16816(acc, a, b0, b1) \
    asm volatile("mma.sync.aligned.m16n8k16.row.col.f32.bf16.bf16.f32 " \
                 "{%0,%1,%2,%3}, {%4,%5,%6,%7}, {%8,%9}, {%0,%1,%2,%3};" \
                 : "+f"((acc)[0]), "+f"((acc)[1]), "+f"((acc)[2]), "+f"((acc)[3]) \
                 : "r"((a)[0]), "r"((a)[1]), "r"((a)[2]), "r"((a)[3]), \
                   "r"(b0), "r"(b1))

// smem layout (bytes). Rows padded to 136 bf16 (272B) -> conflict-free ldmatrix.
#define ROWB 272u
#define IMGB (128u * ROWB)           // 34816 per image
#define SM_W(i) ((i) * IMGB)         // images 0..3
#define SM_AH (4u * IMGB)            // 139264
#define SM_AL (SM_AH + IMGB)         // 174080
#define SM_TOTAL (SM_AL + IMGB)      // 208896

// ---------------------------------------------------------------------------
// Kernel 0: build W^T bf16 hi/lo images (plain [n][k] row-major, k=128 each)
// ---------------------------------------------------------------------------
__global__ void prep_w(const float* __restrict__ Win, const float* __restrict__ Wag) {
    int n = blockIdx.x;     // output feature 0..127
    int kp = threadIdx.x;   // k-pair 0..63
    int k0 = kp * 2;
    float a0 = Win[k0 * 128 + n], a1 = Win[(k0 + 1) * 128 + n];
    float b0 = Wag[k0 * 128 + n], b1 = Wag[(k0 + 1) * 128 + n];
    uint32_t alo, blo;
    uint32_t ahi = pack_split(a0, a1, alo);
    uint32_t bhi = pack_split(b0, b1, blo);
    int idx = n * 64 + kp;
    g_wimg[0 * 8192 + idx] = ahi;
    g_wimg[1 * 8192 + idx] = alo;
    g_wimg[2 * 8192 + idx] = bhi;
    g_wimg[3 * 8192 + idx] = blo;
}

// ---------------------------------------------------------------------------
// Kernel 1: zero the aggregation scratch
// ---------------------------------------------------------------------------
__global__ void zero_kernel(long long n4) {
    long long i = (long long)blockIdx.x * blockDim.x + threadIdx.x;
    long long stride = (long long)gridDim.x * blockDim.x;
    float4 z = make_float4(0.f, 0.f, 0.f, 0.f);
    float4* p = reinterpret_cast<float4*>(g_agg);
    for (; i < n4; i += stride) p[i] = z;
}

// ---------------------------------------------------------------------------
// Kernel 2: scatter-add  g_agg[dst] += h[src]  (one warp per edge)
// ---------------------------------------------------------------------------
__global__ void scatter_kernel(const float* __restrict__ h,
                               const int* __restrict__ src,
                               const int* __restrict__ dst, int E) {
    int warp = (blockIdx.x * blockDim.x + threadIdx.x) >> 5;
    int lane = threadIdx.x & 31;
    if (warp >= E) return;
    int s = __ldg(&src[warp]);
    int d = __ldg(&dst[warp]);
    const float4 v = __ldg(reinterpret_cast<const float4*>(h + (size_t)s * 128) + lane);
    float* p = g_agg + (size_t)d * 128 + lane * 4;
    asm volatile("red.global.add.v4.f32 [%0], {%1,%2,%3,%4};"
                 :: "l"(p), "f"(v.x), "f"(v.y), "f"(v.z), "f"(v.w)
                 : "memory");
}

// ---------------------------------------------------------------------------
// Kernel 3: warp-MMA GEMM + tanh epilogue. One CTA = 128 rows x 128 cols.
// Warp grid 4x2: warp = 32 rows x 64 cols.
// ---------------------------------------------------------------------------
__global__ void __launch_bounds__(256, 1) gemm_mma(
    const float* __restrict__ x, const float* __restrict__ bin,
    const float* __restrict__ baggr, const int* __restrict__ mask,
    float* __restrict__ out, int N) {
    extern __shared__ char smem[];
    const uint32_t sbase = smem_u32(smem);
    const int tid = threadIdx.x;
    const int wid = tid >> 5;
    const int lid = tid & 31;
    const int row0 = blockIdx.x * 128;

    // ---- copy W images (global, plain layout) -> smem (padded rows) ----
    {
        const uint4* src = reinterpret_cast<const uint4*>(g_wimg);
#pragma unroll
        for (int it = 0; it < 32; it++) {
            int idx = tid + it * 256;        // 8192 uint4 total
            int row = idx >> 4;              // 0..511 (img*128 + n)
            int j = idx & 15;
            int img = row >> 7, n = row & 127;
            *reinterpret_cast<uint4*>(smem + SM_W(img) + n * ROWB + j * 16) = src[idx];
        }
    }

    // ---- load + split x tile (mask folded) into AH/AL ----
    const int row_local = tid >> 1;          // 0..127
    const int cbase = (tid & 1) * 64;        // 0 or 64
    const int rg = row0 + row_local;
    const bool ok = (rg < N);
    const float mrow = (ok && (__ldg(&mask[ok ? rg : 0]) != 0)) ? 1.f : 0.f;
    {
        const float4* xs = reinterpret_cast<const float4*>(x + (size_t)(ok ? rg : 0) * 128 + cbase);
#pragma unroll
        for (int j = 0; j < 16; j++) {
            float4 v = ok ? __ldg(xs + j) : make_float4(0.f, 0.f, 0.f, 0.f);
            v.x *= mrow; v.y *= mrow; v.z *= mrow; v.w *= mrow;
            uint32_t lo01, lo23;
            uint32_t hi01 = pack_split(v.x, v.y, lo01);
            uint32_t hi23 = pack_split(v.z, v.w, lo23);
            uint32_t off = row_local * ROWB + (cbase + 4 * j) * 2;
            *reinterpret_cast<uint32_t*>(smem + SM_AH + off) = hi01;
            *reinterpret_cast<uint32_t*>(smem + SM_AH + off + 4) = hi23;
            *reinterpret_cast<uint32_t*>(smem + SM_AL + off) = lo01;
            *reinterpret_cast<uint32_t*>(smem + SM_AL + off + 4) = lo23;
        }
    }
    __syncthreads();

    // ---- warp tile: rows m0..m0+31 (2 m16 tiles), cols n0..n0+63 (8 n8 tiles)
    const int wr = wid >> 1;       // 0..3
    const int wc = wid & 1;        // 0..1
    const int m0 = wr * 32;
    const int n0 = wc * 64;

    float acc[2][8][4];
#pragma unroll
    for (int mt = 0; mt < 2; mt++)
#pragma unroll
        for (int nt = 0; nt < 8; nt++) {
            acc[mt][nt][0] = acc[mt][nt][1] = acc[mt][nt][2] = acc[mt][nt][3] = 0.f;
        }

    // ldmatrix lane-address components
    const int l8 = lid & 7;
    const int quad = lid >> 3;  // 0..3
    // A frag: row = m0 + l8 + (quad&1)*8 ; col = (quad>>1)*8
    const uint32_t a_lane_off =
        (uint32_t)((m0 + l8 + (quad & 1) * 8) * ROWB + ((quad >> 1) * 8) * 2);
    // B frag: row = n0 + l8 + (quad>>1)*8 ; col = (quad&1)*8
    const uint32_t b_lane_off =
        (uint32_t)((n0 + l8 + (quad >> 1) * 8) * ROWB + ((quad & 1) * 8) * 2);

#pragma unroll 1
    for (int phase = 0; phase < 2; phase++) {
        const uint32_t whi = sbase + SM_W(phase * 2) + b_lane_off;
        const uint32_t wlo = sbase + SM_W(phase * 2 + 1) + b_lane_off;
        const uint32_t ahb = sbase + SM_AH + a_lane_off;
        const uint32_t alb = sbase + SM_AL + a_lane_off;

#pragma unroll
        for (int ks = 0; ks < 8; ks++) {
            const uint32_t kb = (uint32_t)(ks * 32);  // k0 * 2 bytes

            // ---- batch all 12 LDSM.x4 up front ----
            uint32_t ah0[4], ah1[4], al0[4], al1[4];
            LDSM_X4(ah0[0], ah0[1], ah0[2], ah0[3], ahb + kb);
            LDSM_X4(ah1[0], ah1[1], ah1[2], ah1[3], ahb + 16 * ROWB + kb);
            LDSM_X4(al0[0], al0[1], al0[2], al0[3], alb + kb);
            LDSM_X4(al1[0], al1[1], al1[2], al1[3], alb + 16 * ROWB + kb);
            uint32_t bh[16], bl[16];
#pragma unroll
            for (int j = 0; j < 4; j++) {
                LDSM_X4(bh[4 * j], bh[4 * j + 1], bh[4 * j + 2], bh[4 * j + 3],
                        whi + (uint32_t)(j * 16 * ROWB) + kb);
            }
#pragma unroll
            for (int j = 0; j < 4; j++) {
                LDSM_X4(bl[4 * j], bl[4 * j + 1], bl[4 * j + 2], bl[4 * j + 3],
                        wlo + (uint32_t)(j * 16 * ROWB) + kb);
            }

            // ---- 48 MMAs: hh (16), lh (16), hl (16) ----
#pragma unroll
            for (int nt = 0; nt < 8; nt++) {
                MMA16816(acc[0][nt], ah0, bh[2 * nt], bh[2 * nt + 1]);
                MMA16816(acc[1][nt], ah1, bh[2 * nt], bh[2 * nt + 1]);
            }
#pragma unroll
            for (int nt = 0; nt < 8; nt++) {
                MMA16816(acc[0][nt], al0, bh[2 * nt], bh[2 * nt + 1]);
                MMA16816(acc[1][nt], al1, bh[2 * nt], bh[2 * nt + 1]);
            }
#pragma unroll
            for (int nt = 0; nt < 8; nt++) {
                MMA16816(acc[0][nt], ah0, bl[2 * nt], bl[2 * nt + 1]);
                MMA16816(acc[1][nt], ah1, bl[2 * nt], bl[2 * nt + 1]);
            }
        }

        if (phase == 0) {
            // rewrite A tiles with agg
            __syncthreads();
            const float4* as =
                reinterpret_cast<const float4*>(g_agg + (size_t)(ok ? rg : 0) * 128 + cbase);
#pragma unroll
            for (int j = 0; j < 16; j++) {
                float4 v = ok ? __ldg(as + j) : make_float4(0.f, 0.f, 0.f, 0.f);
                uint32_t lo01, lo23;
                uint32_t hi01 = pack_split(v.x, v.y, lo01);
                uint32_t hi23 = pack_split(v.z, v.w, lo23);
                uint32_t off = row_local * ROWB + (cbase + 4 * j) * 2;
                *reinterpret_cast<uint32_t*>(smem + SM_AH + off) = hi01;
                *reinterpret_cast<uint32_t*>(smem + SM_AH + off + 4) = hi23;
                *reinterpret_cast<uint32_t*>(smem + SM_AL + off) = lo01;
                *reinterpret_cast<uint32_t*>(smem + SM_AL + off + 4) = lo23;
            }
            __syncthreads();
        }
    }

    // ---- epilogue: acc in regs -> mask*b_in + b_aggr, tanh -> gmem ----
    {
        const int tq = lid >> 2;   // 0..7
        const int t4 = lid & 3;    // 0..3
#pragma unroll
        for (int mt = 0; mt < 2; mt++) {
            const int r1 = row0 + m0 + mt * 16 + tq;
            const int r2 = r1 + 8;
            const float m1 = (r1 < N && __ldg(&mask[r1 < N ? r1 : 0]) != 0) ? 1.f : 0.f;
            const float m2 = (r2 < N && __ldg(&mask[r2 < N ? r2 : 0]) != 0) ? 1.f : 0.f;
#pragma unroll
            for (int nt = 0; nt < 8; nt++) {
                const int c = n0 + nt * 8 + 2 * t4;
                const float bi0 = __ldg(&bin[c]), bi1 = __ldg(&bin[c + 1]);
                const float ba0 = __ldg(&baggr[c]), ba1 = __ldg(&baggr[c + 1]);
                if (r1 < N) {
                    float2 o;
                    o.x = tanh_fast(acc[mt][nt][0] + m1 * bi0 + ba0);
                    o.y = tanh_fast(acc[mt][nt][1] + m1 * bi1 + ba1);
                    *reinterpret_cast<float2*>(&out[(size_t)r1 * 128 + c]) = o;
                }
                if (r2 < N) {
                    float2 o;
                    o.x = tanh_fast(acc[mt][nt][2] + m2 * bi0 + ba0);
                    o.y = tanh_fast(acc[mt][nt][3] + m2 * bi1 + ba1);
                    *reinterpret_cast<float2*>(&out[(size_t)r2 * 128 + c]) = o;
                }
            }
        }
    }
}

// ---------------------------------------------------------------------------
// Launch
// ---------------------------------------------------------------------------
extern "C" void kernel_launch(void* const* d_in, const int* in_sizes, int n_in,
                              void* d_out, int out_size) {
    const float* x     = (const float*)d_in[0];
    const float* h     = (const float*)d_in[1];
    const float* Win   = (const float*)d_in[2];
    const float* bin   = (const float*)d_in[3];
    const float* Waggr = (const float*)d_in[4];
    const float* baggr = (const float*)d_in[5];
    const int* mask    = (const int*)d_in[6];
    const int* esrc    = (const int*)d_in[7];
    const int* edst    = (const int*)d_in[8];
    float* out = (float*)d_out;

    const int N = in_sizes[0] / 128;
    const int E = in_sizes[7];

    static int smem_set = 0;
    if (!smem_set) {
        cudaFuncSetAttribute(gemm_mma, cudaFuncAttributeMaxDynamicSharedMemorySize,
                             (int)SM_TOTAL);
        smem_set = 1;
    }

    prep_w<<<128, 64>>>(Win, Waggr);
    long long n4 = (long long)N * 128 / 4;
    zero_kernel<<<2048, 256>>>(n4);
    scatter_kernel<<<(E + 7) / 8, 256>>>(h, esrc, edst, E);
    gemm_mma<<<(N + 127) / 128, 256, SM_TOTAL>>>(x, bin, baggr, mask, out, N);
}

// round 8
// speedup vs baseline: 1.3538x; 1.3538x over previous
#include <cuda_runtime.h>
#include <cuda_bf16.h>
#include <cstdint>
#include <cstddef>

// ---------------------------------------------------------------------------
// TreeRNNCell: out = tanh( mask*(x@W_in + b_in) + segsum(h[src]->dst)@W_aggr + b_aggr )
// N = 500000, E = 500000, X = H = 128.
//
// R6: warp tile 32x64 (12 LDSM.x4 : 48 MMA) + register double-buffering:
//     LDSMs for k-step ks+1 issue before the MMAs of k-step ks, overlapping
//     the LSU and tensor pipes inside each warp (occ is smem-capped at 8
//     warps, so intra-warp overlap is the only latency cover available).
// ---------------------------------------------------------------------------

#define MAXN 500000
__device__ float g_agg[(size_t)MAXN * 128];
// 4 images: [WinT_hi, WinT_lo, WaggrT_hi, WaggrT_lo], each [128n][128k] bf16
__device__ __align__(16) unsigned int g_wimg[4 * 8192];

__device__ __forceinline__ float tanh_fast(float x) {
    float r; asm("tanh.approx.f32 %0, %1;" : "=f"(r) : "f"(x)); return r;
}
__device__ __forceinline__ uint32_t smem_u32(const void* p) {
    uint32_t a;
    asm("{ .reg .u64 t; cvta.to.shared.u64 t, %1; cvt.u32.u64 %0, t; }" : "=r"(a) : "l"(p));
    return a;
}
__device__ __forceinline__ uint32_t pack_split(float a, float b, uint32_t& lo) {
    __nv_bfloat16 ha = __float2bfloat16(a), hb = __float2bfloat16(b);
    __nv_bfloat16 la = __float2bfloat16(a - __bfloat162float(ha));
    __nv_bfloat16 lb = __float2bfloat16(b - __bfloat162float(hb));
    lo = ((uint32_t)__bfloat16_as_ushort(lb) << 16) | __bfloat16_as_ushort(la);
    return ((uint32_t)__bfloat16_as_ushort(hb) << 16) | __bfloat16_as_ushort(ha);
}

#define LDSM_X4(r0, r1, r2, r3, addr) \
    asm volatile("ldmatrix.sync.aligned.m8n8.x4.shared.b16 {%0,%1,%2,%3}, [%4];" \
                 : "=r"(r0), "=r"(r1), "=r"(r2), "=r"(r3) : "r"(addr))

#define MMA16816(acc, a0, a1, a2, a3, b0, b1) \
    asm volatile("mma.sync.aligned.m16n8k16.row.col.f32.bf16.bf16.f32 " \
                 "{%0,%1,%2,%3}, {%4,%5,%6,%7}, {%8,%9}, {%0,%1,%2,%3};" \
                 : "+f"((acc)[0]), "+f"((acc)[1]), "+f"((acc)[2]), "+f"((acc)[3]) \
                 : "r"(a0), "r"(a1), "r"(a2), "r"(a3), "r"(b0), "r"(b1))

// smem layout (bytes). Rows padded to 136 bf16 (272B) -> conflict-free ldmatrix.
#define ROWB 272u
#define IMGB (128u * ROWB)           // 34816 per image
#define SM_W(i) ((i) * IMGB)         // images 0..3
#define SM_AH (4u * IMGB)            // 139264
#define SM_AL (SM_AH + IMGB)         // 174080
#define SM_TOTAL (SM_AL + IMGB)      // 208896

// Load all 12 LDSM.x4 for one k-step into frag buffer `B` (literal index!)
#define LOAD_K(B, kb)                                                          \
    do {                                                                       \
        LDSM_X4(fa[B][0], fa[B][1], fa[B][2], fa[B][3], ahb + (kb));           \
        LDSM_X4(fa[B][4], fa[B][5], fa[B][6], fa[B][7],                        \
                ahb + 16 * ROWB + (kb));                                       \
        LDSM_X4(fa[B][8], fa[B][9], fa[B][10], fa[B][11], alb + (kb));         \
        LDSM_X4(fa[B][12], fa[B][13], fa[B][14], fa[B][15],                    \
                alb + 16 * ROWB + (kb));                                       \
        LDSM_X4(fbh[B][0], fbh[B][1], fbh[B][2], fbh[B][3], whi + (kb));       \
        LDSM_X4(fbh[B][4], fbh[B][5], fbh[B][6], fbh[B][7],                    \
                whi + 16 * ROWB + (kb));                                       \
        LDSM_X4(fbh[B][8], fbh[B][9], fbh[B][10], fbh[B][11],                  \
                whi + 32 * ROWB + (kb));                                       \
        LDSM_X4(fbh[B][12], fbh[B][13], fbh[B][14], fbh[B][15],                \
                whi + 48 * ROWB + (kb));                                       \
        LDSM_X4(fbl[B][0], fbl[B][1], fbl[B][2], fbl[B][3], wlo + (kb));       \
        LDSM_X4(fbl[B][4], fbl[B][5], fbl[B][6], fbl[B][7],                    \
                wlo + 16 * ROWB + (kb));                                       \
        LDSM_X4(fbl[B][8], fbl[B][9], fbl[B][10], fbl[B][11],                  \
                wlo + 32 * ROWB + (kb));                                       \
        LDSM_X4(fbl[B][12], fbl[B][13], fbl[B][14], fbl[B][15],                \
                wlo + 48 * ROWB + (kb));                                       \
    } while (0)

// 48 MMAs (hh, lh, hl) on frag buffer `B`
#define MMA_K(B)                                                               \
    do {                                                                       \
        _Pragma("unroll") for (int nt = 0; nt < 8; nt++) {                     \
            MMA16816(acc[0][nt], fa[B][0], fa[B][1], fa[B][2], fa[B][3],       \
                     fbh[B][2 * nt], fbh[B][2 * nt + 1]);                      \
            MMA16816(acc[1][nt], fa[B][4], fa[B][5], fa[B][6], fa[B][7],       \
                     fbh[B][2 * nt], fbh[B][2 * nt + 1]);                      \
        }                                                                      \
        _Pragma("unroll") for (int nt = 0; nt < 8; nt++) {                     \
            MMA16816(acc[0][nt], fa[B][8], fa[B][9], fa[B][10], fa[B][11],     \
                     fbh[B][2 * nt], fbh[B][2 * nt + 1]);                      \
            MMA16816(acc[1][nt], fa[B][12], fa[B][13], fa[B][14], fa[B][15],   \
                     fbh[B][2 * nt], fbh[B][2 * nt + 1]);                      \
        }                                                                      \
        _Pragma("unroll") for (int nt = 0; nt < 8; nt++) {                     \
            MMA16816(acc[0][nt], fa[B][0], fa[B][1], fa[B][2], fa[B][3],       \
                     fbl[B][2 * nt], fbl[B][2 * nt + 1]);                      \
            MMA16816(acc[1][nt], fa[B][4], fa[B][5], fa[B][6], fa[B][7],       \
                     fbl[B][2 * nt], fbl[B][2 * nt + 1]);                      \
        }                                                                      \
    } while (0)

// ---------------------------------------------------------------------------
// Kernel 0: build W^T bf16 hi/lo images (plain [n][k] row-major, k=128 each)
// ---------------------------------------------------------------------------
__global__ void prep_w(const float* __restrict__ Win, const float* __restrict__ Wag) {
    int n = blockIdx.x;     // output feature 0..127
    int kp = threadIdx.x;   // k-pair 0..63
    int k0 = kp * 2;
    float a0 = Win[k0 * 128 + n], a1 = Win[(k0 + 1) * 128 + n];
    float b0 = Wag[k0 * 128 + n], b1 = Wag[(k0 + 1) * 128 + n];
    uint32_t alo, blo;
    uint32_t ahi = pack_split(a0, a1, alo);
    uint32_t bhi = pack_split(b0, b1, blo);
    int idx = n * 64 + kp;
    g_wimg[0 * 8192 + idx] = ahi;
    g_wimg[1 * 8192 + idx] = alo;
    g_wimg[2 * 8192 + idx] = bhi;
    g_wimg[3 * 8192 + idx] = blo;
}

// ---------------------------------------------------------------------------
// Kernel 1: zero the aggregation scratch
// ---------------------------------------------------------------------------
__global__ void zero_kernel(long long n4) {
    long long i = (long long)blockIdx.x * blockDim.x + threadIdx.x;
    long long stride = (long long)gridDim.x * blockDim.x;
    float4 z = make_float4(0.f, 0.f, 0.f, 0.f);
    float4* p = reinterpret_cast<float4*>(g_agg);
    for (; i < n4; i += stride) p[i] = z;
}

// ---------------------------------------------------------------------------
// Kernel 2: scatter-add  g_agg[dst] += h[src]  (one warp per edge)
// ---------------------------------------------------------------------------
__global__ void scatter_kernel(const float* __restrict__ h,
                               const int* __restrict__ src,
                               const int* __restrict__ dst, int E) {
    int warp = (blockIdx.x * blockDim.x + threadIdx.x) >> 5;
    int lane = threadIdx.x & 31;
    if (warp >= E) return;
    int s = __ldg(&src[warp]);
    int d = __ldg(&dst[warp]);
    const float4 v = __ldg(reinterpret_cast<const float4*>(h + (size_t)s * 128) + lane);
    float* p = g_agg + (size_t)d * 128 + lane * 4;
    asm volatile("red.global.add.v4.f32 [%0], {%1,%2,%3,%4};"
                 :: "l"(p), "f"(v.x), "f"(v.y), "f"(v.z), "f"(v.w)
                 : "memory");
}

// ---------------------------------------------------------------------------
// Kernel 3: warp-MMA GEMM + tanh epilogue. One CTA = 128 rows x 128 cols.
// Warp grid 4x2: warp = 32 rows x 64 cols. Register double-buffered k-loop.
// ---------------------------------------------------------------------------
__global__ void __launch_bounds__(256, 1) gemm_mma(
    const float* __restrict__ x, const float* __restrict__ bin,
    const float* __restrict__ baggr, const int* __restrict__ mask,
    float* __restrict__ out, int N) {
    extern __shared__ char smem[];
    const uint32_t sbase = smem_u32(smem);
    const int tid = threadIdx.x;
    const int wid = tid >> 5;
    const int lid = tid & 31;
    const int row0 = blockIdx.x * 128;

    // ---- copy W images (global, plain layout) -> smem (padded rows) ----
    {
        const uint4* src = reinterpret_cast<const uint4*>(g_wimg);
#pragma unroll
        for (int it = 0; it < 32; it++) {
            int idx = tid + it * 256;        // 8192 uint4 total
            int row = idx >> 4;              // 0..511 (img*128 + n)
            int j = idx & 15;
            int img = row >> 7, n = row & 127;
            *reinterpret_cast<uint4*>(smem + SM_W(img) + n * ROWB + j * 16) = src[idx];
        }
    }

    // ---- load + split x tile (mask folded) into AH/AL ----
    const int row_local = tid >> 1;          // 0..127
    const int cbase = (tid & 1) * 64;        // 0 or 64
    const int rg = row0 + row_local;
    const bool ok = (rg < N);
    const float mrow = (ok && (__ldg(&mask[ok ? rg : 0]) != 0)) ? 1.f : 0.f;
    {
        const float4* xs = reinterpret_cast<const float4*>(x + (size_t)(ok ? rg : 0) * 128 + cbase);
#pragma unroll
        for (int j = 0; j < 16; j++) {
            float4 v = ok ? __ldg(xs + j) : make_float4(0.f, 0.f, 0.f, 0.f);
            v.x *= mrow; v.y *= mrow; v.z *= mrow; v.w *= mrow;
            uint32_t lo01, lo23;
            uint32_t hi01 = pack_split(v.x, v.y, lo01);
            uint32_t hi23 = pack_split(v.z, v.w, lo23);
            uint32_t off = row_local * ROWB + (cbase + 4 * j) * 2;
            *reinterpret_cast<uint32_t*>(smem + SM_AH + off) = hi01;
            *reinterpret_cast<uint32_t*>(smem + SM_AH + off + 4) = hi23;
            *reinterpret_cast<uint32_t*>(smem + SM_AL + off) = lo01;
            *reinterpret_cast<uint32_t*>(smem + SM_AL + off + 4) = lo23;
        }
    }
    __syncthreads();

    // ---- warp tile: rows m0..m0+31 (2 m16 tiles), cols n0..n0+63 (8 n8 tiles)
    const int wr = wid >> 1;       // 0..3
    const int wc = wid & 1;        // 0..1
    const int m0 = wr * 32;
    const int n0 = wc * 64;

    float acc[2][8][4];
#pragma unroll
    for (int mt = 0; mt < 2; mt++)
#pragma unroll
        for (int nt = 0; nt < 8; nt++) {
            acc[mt][nt][0] = acc[mt][nt][1] = acc[mt][nt][2] = acc[mt][nt][3] = 0.f;
        }

    // ldmatrix lane-address components
    const int l8 = lid & 7;
    const int quad = lid >> 3;  // 0..3
    const uint32_t a_lane_off =
        (uint32_t)((m0 + l8 + (quad & 1) * 8) * ROWB + ((quad >> 1) * 8) * 2);
    const uint32_t b_lane_off =
        (uint32_t)((n0 + l8 + (quad >> 1) * 8) * ROWB + ((quad & 1) * 8) * 2);

    uint32_t fa[2][16], fbh[2][16], fbl[2][16];

#pragma unroll 1
    for (int phase = 0; phase < 2; phase++) {
        const uint32_t whi = sbase + SM_W(phase * 2) + b_lane_off;
        const uint32_t wlo = sbase + SM_W(phase * 2 + 1) + b_lane_off;
        const uint32_t ahb = sbase + SM_AH + a_lane_off;
        const uint32_t alb = sbase + SM_AL + a_lane_off;

        // Pipelined k-loop: load ks+1 before MMAs of ks.
        LOAD_K(0, 0u);
#pragma unroll
        for (int ks = 0; ks < 8; ks += 2) {
            if (ks + 1 < 8) LOAD_K(1, (uint32_t)((ks + 1) * 32));
            MMA_K(0);
            if (ks + 2 < 8) LOAD_K(0, (uint32_t)((ks + 2) * 32));
            MMA_K(1);
        }

        if (phase == 0) {
            // rewrite A tiles with agg
            __syncthreads();
            const float4* as =
                reinterpret_cast<const float4*>(g_agg + (size_t)(ok ? rg : 0) * 128 + cbase);
#pragma unroll
            for (int j = 0; j < 16; j++) {
                float4 v = ok ? __ldg(as + j) : make_float4(0.f, 0.f, 0.f, 0.f);
                uint32_t lo01, lo23;
                uint32_t hi01 = pack_split(v.x, v.y, lo01);
                uint32_t hi23 = pack_split(v.z, v.w, lo23);
                uint32_t off = row_local * ROWB + (cbase + 4 * j) * 2;
                *reinterpret_cast<uint32_t*>(smem + SM_AH + off) = hi01;
                *reinterpret_cast<uint32_t*>(smem + SM_AH + off + 4) = hi23;
                *reinterpret_cast<uint32_t*>(smem + SM_AL + off) = lo01;
                *reinterpret_cast<uint32_t*>(smem + SM_AL + off + 4) = lo23;
            }
            __syncthreads();
        }
    }

    // ---- epilogue: acc in regs -> mask*b_in + b_aggr, tanh -> gmem ----
    {
        const int tq = lid >> 2;   // 0..7
        const int t4 = lid & 3;    // 0..3
#pragma unroll
        for (int mt = 0; mt < 2; mt++) {
            const int r1 = row0 + m0 + mt * 16 + tq;
            const int r2 = r1 + 8;
            const float m1 = (r1 < N && __ldg(&mask[r1 < N ? r1 : 0]) != 0) ? 1.f : 0.f;
            const float m2 = (r2 < N && __ldg(&mask[r2 < N ? r2 : 0]) != 0) ? 1.f : 0.f;
#pragma unroll
            for (int nt = 0; nt < 8; nt++) {
                const int c = n0 + nt * 8 + 2 * t4;
                const float bi0 = __ldg(&bin[c]), bi1 = __ldg(&bin[c + 1]);
                const float ba0 = __ldg(&baggr[c]), ba1 = __ldg(&baggr[c + 1]);
                if (r1 < N) {
                    float2 o;
                    o.x = tanh_fast(acc[mt][nt][0] + m1 * bi0 + ba0);
                    o.y = tanh_fast(acc[mt][nt][1] + m1 * bi1 + ba1);
                    *reinterpret_cast<float2*>(&out[(size_t)r1 * 128 + c]) = o;
                }
                if (r2 < N) {
                    float2 o;
                    o.x = tanh_fast(acc[mt][nt][2] + m2 * bi0 + ba0);
                    o.y = tanh_fast(acc[mt][nt][3] + m2 * bi1 + ba1);
                    *reinterpret_cast<float2*>(&out[(size_t)r2 * 128 + c]) = o;
                }
            }
        }
    }
}

// ---------------------------------------------------------------------------
// Launch
// ---------------------------------------------------------------------------
extern "C" void kernel_launch(void* const* d_in, const int* in_sizes, int n_in,
                              void* d_out, int out_size) {
    const float* x     = (const float*)d_in[0];
    const float* h     = (const float*)d_in[1];
    const float* Win   = (const float*)d_in[2];
    const float* bin   = (const float*)d_in[3];
    const float* Waggr = (const float*)d_in[4];
    const float* baggr = (const float*)d_in[5];
    const int* mask    = (const int*)d_in[6];
    const int* esrc    = (const int*)d_in[7];
    const int* edst    = (const int*)d_in[8];
    float* out = (float*)d_out;

    const int N = in_sizes[0] / 128;
    const int E = in_sizes[7];

    static int smem_set = 0;
    if (!smem_set) {
        cudaFuncSetAttribute(gemm_mma, cudaFuncAttributeMaxDynamicSharedMemorySize,
                             (int)SM_TOTAL);
        smem_set = 1;
    }

    prep_w<<<128, 64>>>(Win, Waggr);
    long long n4 = (long long)N * 128 / 4;
    zero_kernel<<<2048, 256>>>(n4);
    scatter_kernel<<<(E + 7) / 8, 256>>>(h, esrc, edst, E);
    gemm_mma<<<(N + 127) / 128, 256, SM_TOTAL>>>(x, bin, baggr, mask, out, N);
}